// round 13
// baseline (speedup 1.0000x reference)
#include <cuda_runtime.h>
#include <cuda_bf16.h>

#define N_NODES 100000
#define D 32
#define ELL_W 64   // max in-degree; deg ~ Poisson(16), P(>=64) ~ 1e-17 per node

// ------------------------- scratch (__device__ globals) --------------------
__device__ float g_h1[N_NODES * D];         // layer-1 output
__device__ int   g_cnt[N_NODES];            // per-node fill cursor == in-degree
__device__ int   g_ell[N_NODES * ELL_W];    // ELL src-index table

// ---------------------------------------------------------------------------
// Edge-parallel ELL fill, 4 edges per thread (proven R10 version).
__global__ void ell_fill_kernel(const int* __restrict__ src,
                                const int* __restrict__ dst,
                                int* __restrict__ cnt,
                                int* __restrict__ ell, int E) {
    int t = blockIdx.x * blockDim.x + threadIdx.x;
    int e0 = t * 4;
    if (e0 + 3 < E) {
        int4 s = *reinterpret_cast<const int4*>(src + e0);
        int4 d = *reinterpret_cast<const int4*>(dst + e0);
        int sl0 = atomicAdd(&cnt[d.x], 1);
        int sl1 = atomicAdd(&cnt[d.y], 1);
        int sl2 = atomicAdd(&cnt[d.z], 1);
        int sl3 = atomicAdd(&cnt[d.w], 1);
        if (sl0 < ELL_W) ell[d.x * ELL_W + sl0] = s.x;
        if (sl1 < ELL_W) ell[d.y * ELL_W + sl1] = s.y;
        if (sl2 < ELL_W) ell[d.z * ELL_W + sl2] = s.z;
        if (sl3 < ELL_W) ell[d.w * ELL_W + sl3] = s.w;
    } else {
        for (int e = e0; e < E; e++) {
            int sv = src[e], dv = dst[e];
            int slot = atomicAdd(&cnt[dv], 1);
            if (slot < ELL_W) ell[dv * ELL_W + slot] = sv;
        }
    }
}

// ---------------------------------------------------------------------------
// Fully fused SAGE layer, 8 nodes (one octet) per warp iteration:
//   out[n] = relu( mean_{s in N(n)} x[s] @ Wl + b + x[n] @ Wr )
// Gather: R10-proven scheme (2 nodes at a time, 4 edges per LDG.128, direct
//         per-lane index loads, butterfly reduce), staged into smem.
// GEMV:   batched over the 8 staged nodes so the per-lane W smem loads
//         (the expensive, non-broadcast kind) are amortized 8x. Both weight
//         matrices live in smem -> ~64 fewer registers -> 2x occupancy.
__global__ void fused_layer_kernel(
        const float* __restrict__ x,
        const int* __restrict__ cnt,
        const int* __restrict__ ell,
        const float* __restrict__ Wl,
        const float* __restrict__ Wr,
        const float* __restrict__ b,
        float* __restrict__ out, int n) {
    __shared__ float sm[8][8][D];        // [warp][node-in-octet][col] mean rows
    __shared__ float sr[8][8][D];        // [warp][node-in-octet][col] root rows
    __shared__ float sWl[D / 4][D][4];   // [q][lane][j] = Wl[(4q+j)*D + lane]
    __shared__ float sWr[D / 4][D][4];   // [q][lane][j] = Wr[(4q+j)*D + lane]

    int lane = threadIdx.x & 31;
    int wIn = threadIdx.x >> 5;
    int warp = blockIdx.x * 8 + wIn;
    int nWarps = gridDim.x * 8;
    int nOct = (n + 7) >> 3;

    // Stage both weight matrices in smem once per block.
    for (int idx = threadIdx.x; idx < D * D; idx += blockDim.x) {
        int k = idx >> 5;          // row (input dim)
        int c = idx & 31;          // col (output dim)
        sWl[k >> 2][c][k & 3] = Wl[idx];
        sWr[k >> 2][c][k & 3] = Wr[idx];
    }
    float bias = b[lane];
    __syncthreads();

    int egrp = lane >> 3;   // 0..3 : edge within a 4-edge chunk
    int cgrp = lane & 7;    // 0..7 : float4 column group

    for (int o = warp; o < nOct; o += nWarps) {
        int nbase = o * 8;

        // ---- Gather phase: 4 sub-pairs, R10-proven inner loop ----
#pragma unroll
        for (int sp = 0; sp < 4; sp++) {
            int node0 = nbase + 2 * sp;
            int node1 = node0 + 1;
            bool has0 = (node0 < n);
            bool has1 = (node1 < n);
            if (!has0) break;

            int deg0 = cnt[node0];
            int deg1 = has1 ? cnt[node1] : 0;
            int m0 = deg0 < ELL_W ? deg0 : ELL_W;
            int m1 = deg1 < ELL_W ? deg1 : ELL_W;
            const int* row0 = ell + node0 * ELL_W;
            const int* row1 = ell + node1 * ELL_W;

            // Coalesced root-row load (lanes 0-15 cover both nodes).
            int rnode = (lane < 8) ? node0 : node1;
            float4 rootv = make_float4(0.f, 0.f, 0.f, 0.f);
            if (lane < 16 && (lane < 8 || has1)) {
                rootv = *reinterpret_cast<const float4*>(
                    x + (size_t)rnode * D + cgrp * 4);
            }

            // Direct per-lane index loads (independent).
            int id0[8], id1[8];
#pragma unroll
            for (int c = 0; c < 8; c++) {
                int e = c * 4 + egrp;
                id0[c] = (e < m0) ? row0[e] : -1;
                id1[c] = (has1 && e < m1) ? row1[e] : -1;
            }

            float4 acc0 = make_float4(0.f, 0.f, 0.f, 0.f);
            float4 acc1 = make_float4(0.f, 0.f, 0.f, 0.f);
#pragma unroll
            for (int c = 0; c < 8; c++) {
                if (id0[c] >= 0) {
                    float4 v = *reinterpret_cast<const float4*>(
                        x + (size_t)id0[c] * D + cgrp * 4);
                    acc0.x += v.x; acc0.y += v.y; acc0.z += v.z; acc0.w += v.w;
                }
                if (id1[c] >= 0) {
                    float4 v = *reinterpret_cast<const float4*>(
                        x + (size_t)id1[c] * D + cgrp * 4);
                    acc1.x += v.x; acc1.y += v.y; acc1.z += v.z; acc1.w += v.w;
                }
            }
            if (m0 > 32 || m1 > 32) {   // rare tail: deg > 32
#pragma unroll
                for (int c = 0; c < 8; c++) {
                    int e = 32 + c * 4 + egrp;
                    if (e < m0) {
                        float4 v = *reinterpret_cast<const float4*>(
                            x + (size_t)row0[e] * D + cgrp * 4);
                        acc0.x += v.x; acc0.y += v.y; acc0.z += v.z; acc0.w += v.w;
                    }
                    if (has1 && e < m1) {
                        float4 v = *reinterpret_cast<const float4*>(
                            x + (size_t)row1[e] * D + cgrp * 4);
                        acc1.x += v.x; acc1.y += v.y; acc1.z += v.z; acc1.w += v.w;
                    }
                }
            }

            // Butterfly over the 4 edge subgroups.
#pragma unroll
            for (int off = 8; off <= 16; off <<= 1) {
                acc0.x += __shfl_xor_sync(0xffffffffu, acc0.x, off);
                acc0.y += __shfl_xor_sync(0xffffffffu, acc0.y, off);
                acc0.z += __shfl_xor_sync(0xffffffffu, acc0.z, off);
                acc0.w += __shfl_xor_sync(0xffffffffu, acc0.w, off);
                acc1.x += __shfl_xor_sync(0xffffffffu, acc1.x, off);
                acc1.y += __shfl_xor_sync(0xffffffffu, acc1.y, off);
                acc1.z += __shfl_xor_sync(0xffffffffu, acc1.z, off);
                acc1.w += __shfl_xor_sync(0xffffffffu, acc1.w, off);
            }

            float inv0 = 1.0f / fmaxf((float)deg0, 1.0f);
            float inv1 = 1.0f / fmaxf((float)deg1, 1.0f);

            // Stage pre-divided mean rows + root rows (zero-fill missing node).
            if (lane < 8) {
                *reinterpret_cast<float4*>(&sm[wIn][2 * sp][cgrp * 4]) =
                    make_float4(acc0.x * inv0, acc0.y * inv0,
                                acc0.z * inv0, acc0.w * inv0);
                *reinterpret_cast<float4*>(&sr[wIn][2 * sp][cgrp * 4]) = rootv;
            } else if (lane < 16) {
                *reinterpret_cast<float4*>(&sm[wIn][2 * sp + 1][cgrp * 4]) =
                    has1 ? make_float4(acc1.x * inv1, acc1.y * inv1,
                                       acc1.z * inv1, acc1.w * inv1)
                         : make_float4(0.f, 0.f, 0.f, 0.f);
                *reinterpret_cast<float4*>(&sr[wIn][2 * sp + 1][cgrp * 4]) =
                    has1 ? rootv : make_float4(0.f, 0.f, 0.f, 0.f);
            }
        }
        __syncwarp();

        // ---- GEMV phase: 8 nodes, lane = output column ----
        float o0 = bias, o1 = bias, o2 = bias, o3 = bias;
        float o4 = bias, o5 = bias, o6 = bias, o7 = bias;
#pragma unroll
        for (int q = 0; q < D / 4; q++) {
            // Per-lane W loads: amortized over 8 nodes.
            float4 wlq = *reinterpret_cast<const float4*>(&sWl[q][lane][0]);
            float4 wrq = *reinterpret_cast<const float4*>(&sWr[q][lane][0]);
#pragma unroll
            for (int j = 0; j < 8; j++) {
                float4 mj = *reinterpret_cast<const float4*>(&sm[wIn][j][q * 4]);
                float4 rj = *reinterpret_cast<const float4*>(&sr[wIn][j][q * 4]);
                float oj = (j == 0) ? o0 : (j == 1) ? o1 : (j == 2) ? o2 :
                           (j == 3) ? o3 : (j == 4) ? o4 : (j == 5) ? o5 :
                           (j == 6) ? o6 : o7;
                oj = fmaf(mj.x, wlq.x, oj);
                oj = fmaf(mj.y, wlq.y, oj);
                oj = fmaf(mj.z, wlq.z, oj);
                oj = fmaf(mj.w, wlq.w, oj);
                oj = fmaf(rj.x, wrq.x, oj);
                oj = fmaf(rj.y, wrq.y, oj);
                oj = fmaf(rj.z, wrq.z, oj);
                oj = fmaf(rj.w, wrq.w, oj);
                if (j == 0) o0 = oj; else if (j == 1) o1 = oj;
                else if (j == 2) o2 = oj; else if (j == 3) o3 = oj;
                else if (j == 4) o4 = oj; else if (j == 5) o5 = oj;
                else if (j == 6) o6 = oj; else o7 = oj;
            }
        }
        float ov[8] = {o0, o1, o2, o3, o4, o5, o6, o7};
#pragma unroll
        for (int j = 0; j < 8; j++) {
            int node = nbase + j;
            if (node < n)
                out[(size_t)node * D + lane] = fmaxf(ov[j], 0.0f);
        }
        __syncwarp();   // protect smem reuse next iteration
    }
}

// ---------------------------------------------------------------------------
extern "C" void kernel_launch(void* const* d_in, const int* in_sizes, int n_in,
                              void* d_out, int out_size) {
    const float* x = (const float*)d_in[0];
    const int* edge_index = (const int*)d_in[1];   // int32 (JAX x64 disabled)
    const float* W1l = (const float*)d_in[2];
    const float* W1r = (const float*)d_in[3];
    const float* b1  = (const float*)d_in[4];
    const float* W2l = (const float*)d_in[5];
    const float* W2r = (const float*)d_in[6];
    const float* b2  = (const float*)d_in[7];
    float* out = (float*)d_out;

    const int E = in_sizes[1] / 2;
    const int N = N_NODES;
    const int* src = edge_index;
    const int* dst = edge_index + E;

    float* h1;  cudaGetSymbolAddress((void**)&h1, g_h1);
    int* cnt;   cudaGetSymbolAddress((void**)&cnt, g_cnt);
    int* ell;   cudaGetSymbolAddress((void**)&ell, g_ell);

    const int TPB = 256;
    const int nb_fill = ((E + 3) / 4 + TPB - 1) / TPB;   // 4 edges/thread
    const int nOct = (N + 7) / 8;                        // 12500 octets
    const int nb_fused = (nOct + 7) / 8;                 // 1563: 1 octet/warp

    // ---- ELL build (reused by both layers) ----
    cudaMemsetAsync(cnt, 0, N * sizeof(int));
    ell_fill_kernel<<<nb_fill, TPB>>>(src, dst, cnt, ell, E);

    // ---- Layer 1 ----
    fused_layer_kernel<<<nb_fused, TPB>>>(x, cnt, ell, W1l, W1r, b1, h1, N);

    // ---- Layer 2 ----
    fused_layer_kernel<<<nb_fused, TPB>>>(h1, cnt, ell, W2l, W2r, b2, out, N);
}

// round 14
// speedup vs baseline: 1.1217x; 1.1217x over previous
#include <cuda_runtime.h>
#include <cuda_bf16.h>

#define N_NODES 100000
#define D 32
#define ELL_W 64   // max in-degree; deg ~ Poisson(16), P(>=64) ~ 1e-17 per node

// ------------------------- scratch (__device__ globals) --------------------
__device__ float g_h1[N_NODES * D];         // layer-1 output
__device__ int   g_cnt[N_NODES];            // per-node fill cursor == in-degree
__device__ int   g_ell[N_NODES * ELL_W];    // ELL src-index table

// ---------------------------------------------------------------------------
// Edge-parallel ELL fill, 4 edges per thread (proven R10 version).
__global__ void ell_fill_kernel(const int* __restrict__ src,
                                const int* __restrict__ dst,
                                int* __restrict__ cnt,
                                int* __restrict__ ell, int E) {
    int t = blockIdx.x * blockDim.x + threadIdx.x;
    int e0 = t * 4;
    if (e0 + 3 < E) {
        int4 s = *reinterpret_cast<const int4*>(src + e0);
        int4 d = *reinterpret_cast<const int4*>(dst + e0);
        int sl0 = atomicAdd(&cnt[d.x], 1);
        int sl1 = atomicAdd(&cnt[d.y], 1);
        int sl2 = atomicAdd(&cnt[d.z], 1);
        int sl3 = atomicAdd(&cnt[d.w], 1);
        if (sl0 < ELL_W) ell[d.x * ELL_W + sl0] = s.x;
        if (sl1 < ELL_W) ell[d.y * ELL_W + sl1] = s.y;
        if (sl2 < ELL_W) ell[d.z * ELL_W + sl2] = s.z;
        if (sl3 < ELL_W) ell[d.w * ELL_W + sl3] = s.w;
    } else {
        for (int e = e0; e < E; e++) {
            int sv = src[e], dv = dst[e];
            int slot = atomicAdd(&cnt[dv], 1);
            if (slot < ELL_W) ell[dv * ELL_W + slot] = sv;
        }
    }
}

// ---------------------------------------------------------------------------
// Fully fused SAGE layer (R10-proven structure + degree-adaptive gating):
//   out[n] = relu( mean_{s in N(n)} x[s] @ Wl + b + x[n] @ Wr )
// TWO nodes per warp-iteration, grid-stride over node pairs.
// Gather: 4 edges per LDG.128; all 16 index loads issued upfront (predicated,
//         preserves MLP); gather+accumulate gated in 2-chunk segments on the
//         WARP-UNIFORM max degree -> ~32% fewer issued instrs on average.
// GEMV:   lane = output column; Wl,Wr columns in registers; inputs via smem
//         LDS.128 broadcasts (uniform address -> 1-cyc broadcast).
__global__ void __launch_bounds__(256) fused_layer_kernel(
        const float* __restrict__ x,
        const int* __restrict__ cnt,
        const int* __restrict__ ell,
        const float* __restrict__ Wl,
        const float* __restrict__ Wr,
        const float* __restrict__ b,
        float* __restrict__ out, int n) {
    __shared__ float sm[8][2][D];   // [warp][node-in-pair][col] : mean rows
    __shared__ float sr[8][2][D];   // [warp][node-in-pair][col] : root rows

    int lane = threadIdx.x & 31;
    int wIn = threadIdx.x >> 5;
    int warp = blockIdx.x * 8 + wIn;
    int nWarps = gridDim.x * 8;
    int nPairs = (n + 1) >> 1;

    int egrp = lane >> 3;   // 0..3 : edge within a 4-edge chunk
    int cgrp = lane & 7;    // 0..7 : float4 column group

    // Weight columns in registers (lane = output column).
    float wl[D], wr[D];
#pragma unroll
    for (int k = 0; k < D; k++) {
        wl[k] = Wl[k * D + lane];
        wr[k] = Wr[k * D + lane];
    }
    float bias = b[lane];

    for (int p = warp; p < nPairs; p += nWarps) {
        int node0 = p * 2;
        int node1 = node0 + 1;
        bool has1 = (node1 < n);

        int deg0 = cnt[node0];
        int deg1 = has1 ? cnt[node1] : 0;
        int m0 = deg0 < ELL_W ? deg0 : ELL_W;
        int m1 = deg1 < ELL_W ? deg1 : ELL_W;
        int mmax = m0 > m1 ? m0 : m1;       // warp-uniform
        const int* row0 = ell + node0 * ELL_W;
        const int* row1 = ell + node1 * ELL_W;

        // Coalesced root-row load (lanes 0-15 cover both nodes), consumed late.
        int rnode = (lane < 8) ? node0 : node1;
        float4 rootv = make_float4(0.f, 0.f, 0.f, 0.f);
        if (lane < 16 && (lane < 8 || has1)) {
            rootv = *reinterpret_cast<const float4*>(
                x + (size_t)rnode * D + cgrp * 4);
        }

        // Upfront predicated index loads (keep MLP high; off-slots cost only
        // an issue slot, no memory traffic).
        int id0[8], id1[8];
#pragma unroll
        for (int c = 0; c < 8; c++) {
            int e = c * 4 + egrp;
            id0[c] = (e < m0) ? row0[e] : -1;
            id1[c] = (has1 && e < m1) ? row1[e] : -1;
        }

        float4 acc0 = make_float4(0.f, 0.f, 0.f, 0.f);
        float4 acc1 = make_float4(0.f, 0.f, 0.f, 0.f);

        // Segment macro: gather+accumulate chunks [C0, C0+1].
#define GATHER_SEG(C0)                                                        \
        {                                                                     \
            _Pragma("unroll")                                                 \
            for (int c = (C0); c < (C0) + 2; c++) {                           \
                if (id0[c] >= 0) {                                            \
                    float4 v = *reinterpret_cast<const float4*>(              \
                        x + (size_t)id0[c] * D + cgrp * 4);                   \
                    acc0.x += v.x; acc0.y += v.y;                             \
                    acc0.z += v.z; acc0.w += v.w;                             \
                }                                                             \
                if (id1[c] >= 0) {                                            \
                    float4 v = *reinterpret_cast<const float4*>(              \
                        x + (size_t)id1[c] * D + cgrp * 4);                   \
                    acc1.x += v.x; acc1.y += v.y;                             \
                    acc1.z += v.z; acc1.w += v.w;                             \
                }                                                             \
            }                                                                 \
        }

        // Warp-uniform gating: skip segments beyond the max degree.
        GATHER_SEG(0);                      // slots 0..7   (always)
        if (mmax > 8)  GATHER_SEG(2);       // slots 8..15  (~98%)
        if (mmax > 16) GATHER_SEG(4);       // slots 16..23 (~68%)
        if (mmax > 24) GATHER_SEG(6);       // slots 24..31 (~4%)
#undef GATHER_SEG

        // Rare tail: deg > 32 (slots 32..63).
        if (mmax > 32) {
#pragma unroll
            for (int c = 0; c < 8; c++) {
                int e = 32 + c * 4 + egrp;
                if (e < m0) {
                    float4 v = *reinterpret_cast<const float4*>(
                        x + (size_t)row0[e] * D + cgrp * 4);
                    acc0.x += v.x; acc0.y += v.y; acc0.z += v.z; acc0.w += v.w;
                }
                if (has1 && e < m1) {
                    float4 v = *reinterpret_cast<const float4*>(
                        x + (size_t)row1[e] * D + cgrp * 4);
                    acc1.x += v.x; acc1.y += v.y; acc1.z += v.z; acc1.w += v.w;
                }
            }
        }

        // Butterfly over the 4 edge subgroups -> every lane has full sums.
#pragma unroll
        for (int off = 8; off <= 16; off <<= 1) {
            acc0.x += __shfl_xor_sync(0xffffffffu, acc0.x, off);
            acc0.y += __shfl_xor_sync(0xffffffffu, acc0.y, off);
            acc0.z += __shfl_xor_sync(0xffffffffu, acc0.z, off);
            acc0.w += __shfl_xor_sync(0xffffffffu, acc0.w, off);
            acc1.x += __shfl_xor_sync(0xffffffffu, acc1.x, off);
            acc1.y += __shfl_xor_sync(0xffffffffu, acc1.y, off);
            acc1.z += __shfl_xor_sync(0xffffffffu, acc1.z, off);
            acc1.w += __shfl_xor_sync(0xffffffffu, acc1.w, off);
        }

        float inv0 = 1.0f / fmaxf((float)deg0, 1.0f);
        float inv1 = 1.0f / fmaxf((float)deg1, 1.0f);

        // Stage mean rows + root rows in smem.
        if (lane < 8) {
            *reinterpret_cast<float4*>(&sm[wIn][0][cgrp * 4]) =
                make_float4(acc0.x * inv0, acc0.y * inv0,
                            acc0.z * inv0, acc0.w * inv0);
            *reinterpret_cast<float4*>(&sr[wIn][0][cgrp * 4]) = rootv;
        } else if (lane < 16) {
            *reinterpret_cast<float4*>(&sm[wIn][1][cgrp * 4]) =
                make_float4(acc1.x * inv1, acc1.y * inv1,
                            acc1.z * inv1, acc1.w * inv1);
            *reinterpret_cast<float4*>(&sr[wIn][1][cgrp * 4]) = rootv;
        }
        __syncwarp();

        // GEMV, lane = output column.
        float o0 = bias;
        float o1 = bias;
#pragma unroll
        for (int q = 0; q < D / 4; q++) {
            float4 mA = *reinterpret_cast<const float4*>(&sm[wIn][0][q * 4]);
            float4 mB = *reinterpret_cast<const float4*>(&sm[wIn][1][q * 4]);
            float4 rA = *reinterpret_cast<const float4*>(&sr[wIn][0][q * 4]);
            float4 rB = *reinterpret_cast<const float4*>(&sr[wIn][1][q * 4]);
            o0 = fmaf(mA.x, wl[4 * q + 0], o0);
            o0 = fmaf(mA.y, wl[4 * q + 1], o0);
            o0 = fmaf(mA.z, wl[4 * q + 2], o0);
            o0 = fmaf(mA.w, wl[4 * q + 3], o0);
            o0 = fmaf(rA.x, wr[4 * q + 0], o0);
            o0 = fmaf(rA.y, wr[4 * q + 1], o0);
            o0 = fmaf(rA.z, wr[4 * q + 2], o0);
            o0 = fmaf(rA.w, wr[4 * q + 3], o0);
            o1 = fmaf(mB.x, wl[4 * q + 0], o1);
            o1 = fmaf(mB.y, wl[4 * q + 1], o1);
            o1 = fmaf(mB.z, wl[4 * q + 2], o1);
            o1 = fmaf(mB.w, wl[4 * q + 3], o1);
            o1 = fmaf(rB.x, wr[4 * q + 0], o1);
            o1 = fmaf(rB.y, wr[4 * q + 1], o1);
            o1 = fmaf(rB.z, wr[4 * q + 2], o1);
            o1 = fmaf(rB.w, wr[4 * q + 3], o1);
        }
        out[(size_t)node0 * D + lane] = fmaxf(o0, 0.0f);
        if (has1) out[(size_t)node1 * D + lane] = fmaxf(o1, 0.0f);
        __syncwarp();   // protect smem reuse next iteration
    }
}

// ---------------------------------------------------------------------------
extern "C" void kernel_launch(void* const* d_in, const int* in_sizes, int n_in,
                              void* d_out, int out_size) {
    const float* x = (const float*)d_in[0];
    const int* edge_index = (const int*)d_in[1];   // int32 (JAX x64 disabled)
    const float* W1l = (const float*)d_in[2];
    const float* W1r = (const float*)d_in[3];
    const float* b1  = (const float*)d_in[4];
    const float* W2l = (const float*)d_in[5];
    const float* W2r = (const float*)d_in[6];
    const float* b2  = (const float*)d_in[7];
    float* out = (float*)d_out;

    const int E = in_sizes[1] / 2;
    const int N = N_NODES;
    const int* src = edge_index;
    const int* dst = edge_index + E;

    float* h1;  cudaGetSymbolAddress((void**)&h1, g_h1);
    int* cnt;   cudaGetSymbolAddress((void**)&cnt, g_cnt);
    int* ell;   cudaGetSymbolAddress((void**)&ell, g_ell);

    const int TPB = 256;
    const int nb_fill = ((E + 3) / 4 + TPB - 1) / TPB;   // 4 edges/thread
    const int nb_fused = 1184;                           // grid-stride pairs

    // ---- ELL build (reused by both layers) ----
    cudaMemsetAsync(cnt, 0, N * sizeof(int));
    ell_fill_kernel<<<nb_fill, TPB>>>(src, dst, cnt, ell, E);

    // ---- Layer 1 ----
    fused_layer_kernel<<<nb_fused, TPB>>>(x, cnt, ell, W1l, W1r, b1, h1, N);

    // ---- Layer 2 ----
    fused_layer_kernel<<<nb_fused, TPB>>>(h1, cnt, ell, W2l, W2r, b2, out, N);
}